// round 4
// baseline (speedup 1.0000x reference)
#include <cuda_runtime.h>
#include <cuda_bf16.h>

// Shapes (fixed by the reference)
#define B_   32
#define C_   512
#define N_   1024       // H*W
#define M_   77
#define MP_  128        // padded M
#define TD_  768
#define NH_  8
#define HD_  64
#define SCALE_ 0.125f   // 1/sqrt(64)

// Scratch (static __device__ — allocation-free per harness rules)
__device__ float g_Qt[B_ * C_ * N_];     // 64 MB  Qt[b][c][n]
__device__ float g_Kt[B_ * C_ * MP_];    //  8 MB  Kt[b][c][m]
__device__ float g_Vt[B_ * C_ * MP_];    //  8 MB
__device__ float g_textT[B_ * TD_ * MP_];// 12 MB  textT[b][t][m] (zero padded m>=77)

typedef unsigned long long ull;
union F2U { float2 f; ull u; };
union F4U { float4 v; ull u[2]; float f[4]; };

// Packed fp32x2 FMA (Blackwell FFMA2 — only reachable via PTX)
__device__ __forceinline__ ull ffma2(ull a, ull b, ull c) {
    ull d;
    asm("fma.rn.f32x2 %0, %1, %2, %3;" : "=l"(d) : "l"(a), "l"(b), "l"(c));
    return d;
}
__device__ __forceinline__ ull pack2(float x, float y) {
    ull r; asm("mov.b64 %0, {%1, %2};" : "=l"(r) : "f"(x), "f"(y)); return r;
}
__device__ __forceinline__ float2 unpack2(ull v) {
    float2 r; asm("mov.b64 {%0, %1}, %2;" : "=f"(r.x), "=f"(r.y) : "l"(v)); return r;
}

// ---------------------------------------------------------------------------
// 1) text_emb [B][77][768] -> textT [B][768][128], zero-padded in m
// ---------------------------------------------------------------------------
__global__ void transpose_text_kernel(const float* __restrict__ text) {
    __shared__ float tile[32][33];
    const int b  = blockIdx.z;
    const int t0 = blockIdx.x << 5;   // over 768 (24 blocks)
    const int m0 = blockIdx.y << 5;   // over 128 (4 blocks)
    const int tx = threadIdx.x, ty = threadIdx.y;
#pragma unroll
    for (int i = ty; i < 32; i += 8) {
        const int m = m0 + i;
        float v = 0.0f;
        if (m < M_) v = text[(b * M_ + m) * TD_ + t0 + tx];
        tile[i][tx] = v;
    }
    __syncthreads();
#pragma unroll
    for (int i = ty; i < 32; i += 8) {
        g_textT[(b * TD_ + t0 + i) * MP_ + m0 + tx] = tile[tx][i];
    }
}

// ---------------------------------------------------------------------------
// 2) SGEMM 128x128x8, 256 threads, 8x8 microtile, FFMA2 inner product.
//    C[row][col] = sum_k A[row][k] * B[k][col] + bias[row]
//    All dims are multiples of the tile sizes -> no guards.
// ---------------------------------------------------------------------------
__device__ __forceinline__ void sgemm_body(
    const float* __restrict__ A, const float* __restrict__ B,
    float* __restrict__ C, const float* __restrict__ bias,
    int K, int ldb, int ldc)
{
    __shared__ float As[8][128];
    __shared__ float Bs[8][128];

    const int tid     = threadIdx.x;
    const int rowBase = blockIdx.y << 7;
    const int colBase = blockIdx.x << 7;

    const int a_m = tid >> 1, a_k = (tid & 1) << 2;     // A tile loader
    const int b_k = tid >> 5, b_n = (tid & 31) << 2;    // B tile loader
    const int m0  = (tid >> 4) << 3, n0 = (tid & 15) << 3;

    const float* Aptr = A + (rowBase + a_m) * K + a_k;
    const float* Bptr = B + b_k * ldb + colBase + b_n;

    ull acc[8][4];
#pragma unroll
    for (int i = 0; i < 8; i++)
#pragma unroll
        for (int j = 0; j < 4; j++) acc[i][j] = 0ull;

    float4 aReg = *reinterpret_cast<const float4*>(Aptr);
    float4 bReg = *reinterpret_cast<const float4*>(Bptr);

    const int nT = K >> 3;
    for (int t = 0; t < nT; t++) {
        As[a_k + 0][a_m] = aReg.x;
        As[a_k + 1][a_m] = aReg.y;
        As[a_k + 2][a_m] = aReg.z;
        As[a_k + 3][a_m] = aReg.w;
        *reinterpret_cast<float4*>(&Bs[b_k][b_n]) = bReg;
        __syncthreads();
        if (t + 1 < nT) {   // prefetch next tile; LDG hidden under compute
            aReg = *reinterpret_cast<const float4*>(Aptr + (t + 1) * 8);
            bReg = *reinterpret_cast<const float4*>(Bptr + (t + 1) * 8 * ldb);
        }
#pragma unroll
        for (int kk = 0; kk < 8; kk++) {
            F4U a0; a0.v = *reinterpret_cast<const float4*>(&As[kk][m0]);
            F4U a1; a1.v = *reinterpret_cast<const float4*>(&As[kk][m0 + 4]);
            F4U b0; b0.v = *reinterpret_cast<const float4*>(&Bs[kk][n0]);
            F4U b1; b1.v = *reinterpret_cast<const float4*>(&Bs[kk][n0 + 4]);
            ull bb[4] = { b0.u[0], b0.u[1], b1.u[0], b1.u[1] };
            ull ad[8];
#pragma unroll
            for (int i = 0; i < 4; i++) {
                ad[i]     = pack2(a0.f[i], a0.f[i]);
                ad[4 + i] = pack2(a1.f[i], a1.f[i]);
            }
#pragma unroll
            for (int i = 0; i < 8; i++)
#pragma unroll
                for (int j = 0; j < 4; j++)
                    acc[i][j] = ffma2(ad[i], bb[j], acc[i][j]);
        }
        __syncthreads();
    }

#pragma unroll
    for (int i = 0; i < 8; i++) {
        const int r = rowBase + m0 + i;
        const float bi = bias[r];
        float* crow = C + r * ldc + colBase + n0;
        F2U p0, p1, p2, p3;
        p0.u = acc[i][0]; p1.u = acc[i][1]; p2.u = acc[i][2]; p3.u = acc[i][3];
        float4 o0 = make_float4(p0.f.x + bi, p0.f.y + bi, p1.f.x + bi, p1.f.y + bi);
        float4 o1 = make_float4(p2.f.x + bi, p2.f.y + bi, p3.f.x + bi, p3.f.y + bi);
        *reinterpret_cast<float4*>(crow)     = o0;
        *reinterpret_cast<float4*>(crow + 4) = o1;
    }
}

// Qt[b] = Wq(512x512) @ x[b](512x1024) + bq     grid (8,4,32)
__global__ __launch_bounds__(256, 2)
void sgemm_q_kernel(const float* __restrict__ Wq, const float* __restrict__ x,
                    const float* __restrict__ bq) {
    const int b = blockIdx.z;
    sgemm_body(Wq, x + b * C_ * N_, g_Qt + b * C_ * N_, bq, C_, N_, N_);
}

// Kt/Vt[b] = W(512x768) @ textT[b](768x128) + bias   grid (1,4,64), z = 2*b+sel
__global__ __launch_bounds__(256, 2)
void sgemm_kv_kernel(const float* __restrict__ Wk, const float* __restrict__ Wv,
                     const float* __restrict__ bk, const float* __restrict__ bv) {
    const int z = blockIdx.z;
    const int b = z >> 1;
    const bool isV = (z & 1) != 0;
    const float* A    = isV ? Wv : Wk;
    const float* bias = isV ? bv : bk;
    float* Cout = (isV ? g_Vt : g_Kt) + b * C_ * MP_;
    sgemm_body(A, g_textT + b * TD_ * MP_, Cout, bias, TD_, MP_, MP_);
}

// ---------------------------------------------------------------------------
// 3) Fused attention: block = (n-tile of 128, head, batch), 1 query / thread.
//    K/V head tiles in smem; scores in registers (M=77 fully unrolled);
//    output written directly in [B][C][H][W] layout (coalesced over n).
// ---------------------------------------------------------------------------
__global__ __launch_bounds__(128)
void attn_kernel(const int* __restrict__ mask, float* __restrict__ out) {
    __shared__ float Ksm[M_][68];   // [m][d], stride 68 keeps float4 reads aligned
    __shared__ float Vsm[M_][68];
    __shared__ float msk[M_];

    const int tid = threadIdx.x;
    const int b = blockIdx.z, h = blockIdx.y;
    const int n = (blockIdx.x << 7) + tid;

    const int kvBase = (b * C_ + h * HD_) * MP_;
    const int qBase  = (b * C_ + h * HD_) * N_ + n;

    // Per-thread query vector, 32 packed pairs (coalesced over n)
    ull q2[32];
#pragma unroll
    for (int j = 0; j < 32; j++) {
        float qx = g_Qt[qBase + (2 * j) * N_];
        float qy = g_Qt[qBase + (2 * j + 1) * N_];
        q2[j] = pack2(qx, qy);
    }

    if (tid < M_) {
#pragma unroll 4
        for (int d = 0; d < HD_; d++) {
            Ksm[tid][d] = g_Kt[kvBase + d * MP_ + tid];   // coalesced over m
            Vsm[tid][d] = g_Vt[kvBase + d * MP_ + tid];
        }
        msk[tid] = (mask[b * M_ + tid] != 0) ? 1.0f : 0.0f;
    }
    __syncthreads();

    // scores: s[m] = q . K[m]
    float s[M_];
#pragma unroll
    for (int m = 0; m < M_; m++) {
        ull c0 = 0ull, c1 = 0ull, c2 = 0ull, c3 = 0ull;   // 4 chains hide FFMA lat
#pragma unroll
        for (int j = 0; j < 8; j++) {
            F4U k0; k0.v = *reinterpret_cast<const float4*>(&Ksm[m][j * 8]);
            F4U k1; k1.v = *reinterpret_cast<const float4*>(&Ksm[m][j * 8 + 4]);
            c0 = ffma2(q2[4 * j + 0], k0.u[0], c0);
            c1 = ffma2(q2[4 * j + 1], k0.u[1], c1);
            c2 = ffma2(q2[4 * j + 2], k1.u[0], c2);
            c3 = ffma2(q2[4 * j + 3], k1.u[1], c3);
        }
        float2 r0 = unpack2(c0), r1 = unpack2(c1), r2 = unpack2(c2), r3 = unpack2(c3);
        s[m] = ((r0.x + r0.y) + (r1.x + r1.y)) + ((r2.x + r2.y) + (r3.x + r3.y));
    }

    // masked softmax over m
    float mx = -1e30f;
#pragma unroll
    for (int m = 0; m < M_; m++) {
        s[m] = (msk[m] != 0.0f) ? s[m] * SCALE_ : -1e30f;
        mx = fmaxf(mx, s[m]);
    }
    float sum = 0.0f;
#pragma unroll
    for (int m = 0; m < M_; m++) {
        float p = __expf(s[m] - mx);
        s[m] = p;
        sum += p;
    }
    const float inv = 1.0f / sum;

    // out = P @ V
    ull o2[32];
#pragma unroll
    for (int j = 0; j < 32; j++) o2[j] = 0ull;
#pragma unroll
    for (int m = 0; m < M_; m++) {
        ull pm = pack2(s[m], s[m]);
#pragma unroll
        for (int j = 0; j < 16; j++) {
            F4U v4; v4.v = *reinterpret_cast<const float4*>(&Vsm[m][j * 4]);
            o2[2 * j]     = ffma2(pm, v4.u[0], o2[2 * j]);
            o2[2 * j + 1] = ffma2(pm, v4.u[1], o2[2 * j + 1]);
        }
    }
#pragma unroll
    for (int j = 0; j < 32; j++) {
        float2 o = unpack2(o2[j]);
        out[qBase + (2 * j) * N_]     = o.x * inv;   // same layout as Qt = [B][C][N]
        out[qBase + (2 * j + 1) * N_] = o.y * inv;
    }
}

// ---------------------------------------------------------------------------
// kernel_launch — inputs per metadata order:
// 0:x 1:text_emb 2:attention_mask 3:Wq 4:bq 5:Wk 6:bk 7:Wv 8:bv
// ---------------------------------------------------------------------------
extern "C" void kernel_launch(void* const* d_in, const int* in_sizes, int n_in,
                              void* d_out, int out_size) {
    (void)in_sizes; (void)n_in; (void)out_size;
    const float* x    = (const float*)d_in[0];
    const float* text = (const float*)d_in[1];
    const int*   mask = (const int*)d_in[2];
    const float* Wq   = (const float*)d_in[3];
    const float* bq   = (const float*)d_in[4];
    const float* Wk   = (const float*)d_in[5];
    const float* bk   = (const float*)d_in[6];
    const float* Wv   = (const float*)d_in[7];
    const float* bv   = (const float*)d_in[8];
    float* out = (float*)d_out;

    transpose_text_kernel<<<dim3(24, 4, 32), dim3(32, 8)>>>(text);
    sgemm_kv_kernel<<<dim3(1, 4, 64), 256>>>(Wk, Wv, bk, bv);
    sgemm_q_kernel<<<dim3(8, 4, 32), 256>>>(Wq, x, bq);
    attn_kernel<<<dim3(8, 8, 32), 128>>>(mask, out);
}